// round 11
// baseline (speedup 1.0000x reference)
#include <cuda_runtime.h>
#include <cuda_fp16.h>
#include <math.h>
#include <stdint.h>

// Problem constants
#define Bc 4
#define Sc 2048
#define Ec 1024
#define Hc 16
#define Dc 64
#define Mtot (Bc*Sc)   // 8192
#define Kdim 1024

// gemm_out tiling: 128x128 CTA, 8 warps (64x32), KT=64/barrier, 3-stage
#define MT 128
#define NT 128
#define KT2 64
#define KTILES2 (Kdim/KT2)            // 16
#define GPH 72                         // halves pitch
#define STAGE_BYTES (MT*GPH*2)        // 18432
#define OUT_B_OFF  (3*STAGE_BYTES)    // 55296
#define OUT_SMEM   (6*STAGE_BYTES)    // 110592

// qkv tiling: 128x128 CTA, 8 warps (64x32), KT=32/barrier, 3-stage, A fp32
#define KT1 32
#define KTILES1 (Kdim/KT1)            // 32
#define QKV_A_STAGE 20480             // 128*40*4 (pitch 40 floats)
#define QKV_B_BASE  61440             // 3 A stages
#define QKV_B_STAGE 10240             // 128*40*2 (pitch 40 halves)
#define QKV_SMEM    92160

// Scratch (allocation-free: __device__ globals)
__device__ __half g_kp[Bc*Hc*Sc*Dc];   // [B,H,S,D]
__device__ __half g_vp[Bc*Hc*Sc*Dc];
__device__ __half g_qp[Bc*Hc*Sc*Dc];   // pre-scaled by 1/8
__device__ __half g_ctx[Bc*Sc*Ec];     // [B,S,E]
__device__ __half g_rW[4*Ec*Ec];       // fp16 weights

// ---------------------------------------------------------------------------
// helpers
// ---------------------------------------------------------------------------
__device__ __forceinline__ uint32_t smem_u32(const void* p) {
    uint32_t a;
    asm("{ .reg .u64 t; cvta.to.shared.u64 t, %1; cvt.u32.u64 %0, t; }" : "=r"(a) : "l"(p));
    return a;
}
#define CP_ASYNC16(dst, src) \
    asm volatile("cp.async.cg.shared.global [%0], [%1], 16;" :: "r"(dst), "l"(src))
#define CP_COMMIT() asm volatile("cp.async.commit_group;" ::: "memory")
#define CP_WAIT(n)  asm volatile("cp.async.wait_group %0;" :: "n"(n) : "memory")

#define MMA_F16(d, a, b) \
    asm volatile("mma.sync.aligned.m16n8k16.row.col.f32.f16.f16.f32 " \
        "{%0,%1,%2,%3}, {%4,%5,%6,%7}, {%8,%9}, {%0,%1,%2,%3};" \
        : "+f"((d)[0]), "+f"((d)[1]), "+f"((d)[2]), "+f"((d)[3]) \
        : "r"((a)[0]), "r"((a)[1]), "r"((a)[2]), "r"((a)[3]), \
          "r"((b)[0]), "r"((b)[1]))

#define LDMATRIX_X4(r0, r1, r2, r3, addr) \
    asm volatile("ldmatrix.sync.aligned.m8n8.x4.shared.b16 {%0,%1,%2,%3}, [%4];" \
        : "=r"(r0), "=r"(r1), "=r"(r2), "=r"(r3) : "r"(addr))

#define LDMATRIX_X4_TRANS(r0, r1, r2, r3, addr) \
    asm volatile("ldmatrix.sync.aligned.m8n8.x4.trans.shared.b16 {%0,%1,%2,%3}, [%4];" \
        : "=r"(r0), "=r"(r1), "=r"(r2), "=r"(r3) : "r"(addr))

__device__ __forceinline__ uint32_t h2u(__half2 h) { return *(uint32_t*)&h; }

// ---------------------------------------------------------------------------
// weight convert: 4 weights fp32 -> fp16
// ---------------------------------------------------------------------------
#define NW8 (Ec*Ec/8)   // 131072 chunks per weight
__global__ __launch_bounds__(256) void cvt_weights_kernel(const float4* __restrict__ w0,
                                                          const float4* __restrict__ w1,
                                                          const float4* __restrict__ w2,
                                                          const float4* __restrict__ w3) {
    int i = blockIdx.x * blockDim.x + threadIdx.x;
    int w = i >> 17;
    int idx = i & (NW8 - 1);
    const float4* src = (w == 0) ? w0 : (w == 1) ? w1 : (w == 2) ? w2 : w3;
    float4 a = src[2 * idx], b = src[2 * idx + 1];
    uint4 r;
    r.x = h2u(__floats2half2_rn(a.x, a.y));
    r.y = h2u(__floats2half2_rn(a.z, a.w));
    r.z = h2u(__floats2half2_rn(b.x, b.y));
    r.w = h2u(__floats2half2_rn(b.z, b.w));
    ((uint4*)(g_rW + (size_t)w * Ec * Ec))[idx] = r;
}

// ---------------------------------------------------------------------------
// QKV GEMM: fp32 A direct (convert in registers). 3-stage KT=32.
// z: (k,Wk)->g_kp, (v,Wv)->g_vp, (q,Wq)->g_qp*0.125
// ---------------------------------------------------------------------------
__global__ __launch_bounds__(256, 2) void gemm_qkv(const float* __restrict__ Ak,
                                                   const float* __restrict__ Av,
                                                   const float* __restrict__ Aq)
{
    extern __shared__ char smc[];
    float* Asf = (float*)smc;                           // [3][128][40]
    const uint32_t smb  = smem_u32(smc);
    const uint32_t smbB = smb + QKV_B_BASE;

    const int tid  = threadIdx.x;
    const int wid  = tid >> 5;
    const int lane = tid & 31;
    const int warp_m = wid & 1;       // 64-row band
    const int warp_n = wid >> 1;      // 32-col band
    const int fr = lane >> 2;
    const int fc = lane & 3;
    const int l16 = lane & 15;
    const int lh  = lane >> 4;

    const int z  = blockIdx.z;
    const int n0 = blockIdx.x * NT;
    const int m0 = blockIdx.y * MT;

    const float* A = (z == 0) ? Ak : (z == 1) ? Av : Aq;
    const __half* W = g_rW + (size_t)z * Ec * Ec;
    __half* outp = (z == 0) ? g_kp : (z == 1) ? g_vp : g_qp;
    const float scale = (z == 2) ? 0.125f : 1.0f;

    auto load_tile = [&](int kt, int buf) {
        const int k0 = kt * KT1;
        #pragma unroll
        for (int i = 0; i < 4; i++) {                   // A: 1024 chunks fp32
            int c = tid + i * 256;
            int row = c >> 3, seg = c & 7;
            CP_ASYNC16(smb + buf * QKV_A_STAGE + row * 160 + seg * 16,
                       A + (size_t)(m0 + row) * Kdim + k0 + seg * 4);
        }
        #pragma unroll
        for (int i = 0; i < 2; i++) {                   // B: 512 chunks fp16
            int c = tid + i * 256;
            int row = c >> 2, seg = c & 3;
            CP_ASYNC16(smbB + buf * QKV_B_STAGE + row * 80 + seg * 16,
                       W + (size_t)(n0 + row) * Kdim + k0 + seg * 8);
        }
    };

    float acc[4][4][4];
    #pragma unroll
    for (int i = 0; i < 4; i++)
        #pragma unroll
        for (int j = 0; j < 4; j++)
            #pragma unroll
            for (int r = 0; r < 4; r++) acc[i][j][r] = 0.0f;

    load_tile(0, 0); CP_COMMIT();
    load_tile(1, 1); CP_COMMIT();

    int buf = 0, nbuf = 2;
    for (int kt = 0; kt < KTILES1; kt++) {
        CP_WAIT(1);
        __syncthreads();
        if (kt + 2 < KTILES1) load_tile(kt + 2, nbuf);
        CP_COMMIT();

        const float* Ab = Asf + buf * (128 * 40);
        const uint32_t bB = smbB + buf * QKV_B_STAGE;

        // B frags for both k16-steps up-front (4 LDSM)
        uint32_t bf[2][4][2];
        #pragma unroll
        for (int s = 0; s < 2; s++) {
            #pragma unroll
            for (int np = 0; np < 2; np++) {
                uint32_t r0, r1, r2, r3;
                uint32_t addr = bB + (uint32_t)(warp_n * 32 + np * 16 + l16) * 80
                                   + (uint32_t)(s * 16 + lh * 8) * 2;
                LDMATRIX_X4(r0, r1, r2, r3, addr);
                bf[s][2 * np][0] = r0; bf[s][2 * np][1] = r2;
                bf[s][2 * np + 1][0] = r1; bf[s][2 * np + 1][1] = r3;
            }
        }

        #pragma unroll
        for (int s = 0; s < 2; s++) {
            const int ks = s * 16;
            uint32_t af[4][4];
            #pragma unroll
            for (int mt = 0; mt < 4; mt++) {
                int row = warp_m * 64 + mt * 16 + fr;
                float2 f0 = *(const float2*)&Ab[row * 40 + ks + 2 * fc];
                float2 f1 = *(const float2*)&Ab[(row + 8) * 40 + ks + 2 * fc];
                float2 f2 = *(const float2*)&Ab[row * 40 + ks + 2 * fc + 8];
                float2 f3 = *(const float2*)&Ab[(row + 8) * 40 + ks + 2 * fc + 8];
                af[mt][0] = h2u(__floats2half2_rn(f0.x, f0.y));
                af[mt][1] = h2u(__floats2half2_rn(f1.x, f1.y));
                af[mt][2] = h2u(__floats2half2_rn(f2.x, f2.y));
                af[mt][3] = h2u(__floats2half2_rn(f3.x, f3.y));
            }
            #pragma unroll
            for (int mt = 0; mt < 4; mt++)
                #pragma unroll
                for (int nt = 0; nt < 4; nt++)
                    MMA_F16(acc[mt][nt], af[mt], bf[s][nt]);
        }

        buf = (buf == 2) ? 0 : buf + 1;
        nbuf = (nbuf == 2) ? 0 : nbuf + 1;
    }

    // scatter epilogue: half2 into [B,H,S,D]
    #pragma unroll
    for (int mt = 0; mt < 4; mt++)
        #pragma unroll
        for (int nt = 0; nt < 4; nt++) {
            int n = n0 + warp_n * 32 + nt * 8 + fc * 2;
            #pragma unroll
            for (int hi = 0; hi < 2; hi++) {
                int m = m0 + warp_m * 64 + mt * 16 + fr + hi * 8;
                int b = m >> 11, s = m & 2047;
                int h = n >> 6,  d = n & 63;
                __half2 hv = __floats2half2_rn(acc[mt][nt][hi * 2] * scale,
                                               acc[mt][nt][hi * 2 + 1] * scale);
                *(__half2*)&outp[(size_t)(((b * Hc + h) * Sc) + s) * Dc + d] = hv;
            }
        }
}

// ---------------------------------------------------------------------------
// Output GEMM (R8 config): fp16 A=g_ctx, KT=64, 3-stage, up-front frags.
// ---------------------------------------------------------------------------
__global__ __launch_bounds__(256, 2) void gemm_out(float* __restrict__ Cout)
{
    extern __shared__ char smc[];
    const uint32_t smbA = smem_u32(smc);
    const uint32_t smbB = smbA + OUT_B_OFF;

    const int tid  = threadIdx.x;
    const int wid  = tid >> 5;
    const int lane = tid & 31;
    const int warp_m = wid & 1;
    const int warp_n = wid >> 1;
    const int fr = lane >> 2;
    const int fc = lane & 3;
    const int l16 = lane & 15;
    const int lh  = lane >> 4;

    const int n0 = blockIdx.x * NT;
    const int m0 = blockIdx.y * MT;
    const __half* A = g_ctx;
    const __half* W = g_rW + (size_t)3 * Ec * Ec;

    auto load_tile = [&](int kt, int buf) {
        const int k0 = kt * KT2;
        #pragma unroll
        for (int i = 0; i < 4; i++) {
            int c = tid + i * 256;
            int row = c >> 3, seg = c & 7;
            CP_ASYNC16(smbA + buf * STAGE_BYTES + row * (GPH * 2) + seg * 16,
                       A + (size_t)(m0 + row) * Kdim + k0 + seg * 8);
            CP_ASYNC16(smbB + buf * STAGE_BYTES + row * (GPH * 2) + seg * 16,
                       W + (size_t)(n0 + row) * Kdim + k0 + seg * 8);
        }
    };

    float acc[4][4][4];
    #pragma unroll
    for (int i = 0; i < 4; i++)
        #pragma unroll
        for (int j = 0; j < 4; j++)
            #pragma unroll
            for (int r = 0; r < 4; r++) acc[i][j][r] = 0.0f;

    load_tile(0, 0); CP_COMMIT();
    load_tile(1, 1); CP_COMMIT();

    int buf = 0, nbuf = 2;
    for (int kt = 0; kt < KTILES2; kt++) {
        CP_WAIT(1);
        __syncthreads();
        if (kt + 2 < KTILES2) load_tile(kt + 2, nbuf);
        CP_COMMIT();

        const uint32_t bA = smbA + buf * STAGE_BYTES;
        const uint32_t bB = smbB + buf * STAGE_BYTES;

        #pragma unroll
        for (int s = 0; s < 4; s++) {
            uint32_t af[4][4], bf[4][2];
            #pragma unroll
            for (int mt = 0; mt < 4; mt++) {
                uint32_t addr = bA + (uint32_t)(warp_m * 64 + mt * 16 + l16) * (GPH * 2)
                                   + (uint32_t)(s * 16 + lh * 8) * 2;
                LDMATRIX_X4(af[mt][0], af[mt][1], af[mt][2], af[mt][3], addr);
            }
            #pragma unroll
            for (int np = 0; np < 2; np++) {
                uint32_t r0, r1, r2, r3;
                uint32_t addr = bB + (uint32_t)(warp_n * 32 + np * 16 + l16) * (GPH * 2)
                                   + (uint32_t)(s * 16 + lh * 8) * 2;
                LDMATRIX_X4(r0, r1, r2, r3, addr);
                bf[2 * np][0] = r0; bf[2 * np][1] = r2;
                bf[2 * np + 1][0] = r1; bf[2 * np + 1][1] = r3;
            }
            #pragma unroll
            for (int mt = 0; mt < 4; mt++)
                #pragma unroll
                for (int nt = 0; nt < 4; nt++)
                    MMA_F16(acc[mt][nt], af[mt], bf[nt]);
        }

        buf = (buf == 2) ? 0 : buf + 1;
        nbuf = (nbuf == 2) ? 0 : nbuf + 1;
    }

    #pragma unroll
    for (int mt = 0; mt < 4; mt++)
        #pragma unroll
        for (int nt = 0; nt < 4; nt++) {
            int n = n0 + warp_n * 32 + nt * 8 + fc * 2;
            #pragma unroll
            for (int hi = 0; hi < 2; hi++) {
                int m = m0 + warp_m * 64 + mt * 16 + fr + hi * 8;
                *(float2*)&Cout[(size_t)m * Ec + n] =
                    make_float2(acc[mt][nt][hi * 2], acc[mt][nt][hi * 2 + 1]);
            }
        }
}

// ---------------------------------------------------------------------------
// Tensor-core flash attention (causal), fp16 mma.sync (fp32 accum).
// ---------------------------------------------------------------------------
#define ATTN_SMEM_BYTES ((9216 + 9216 + 9216) * 2)   // 55296

__global__ __launch_bounds__(256) void attn_tc_kernel()
{
    extern __shared__ __half sh[];
    const int tid  = threadIdx.x;
    const int wq   = tid >> 5;
    const int lane = tid & 31;
    const int fr   = lane >> 2;
    const int fc   = lane & 3;
    const int l16  = lane & 15;
    const int lh   = lane >> 4;
    const int b    = blockIdx.z;
    const int h    = blockIdx.y;
    const int qb   = (int)(gridDim.x - 1 - blockIdx.x);   // heavy tiles first

    const size_t bh = (size_t)(b * Hc + h) * Sc;
    const __half* kg = g_kp + bh * Dc;
    const __half* vg = g_vp + bh * Dc;

    __half* Pw = sh + 18432 + wq * 16 * 72;
    const uint32_t smb = smem_u32(sh);
    const uint32_t pw_base = smb + (uint32_t)(18432 + wq * 16 * 72) * 2;

    {
        const __half* qg = g_qp + (bh + (size_t)qb * 128) * Dc;
        #pragma unroll
        for (int i = 0; i < 4; i++) {
            int c = tid + i * 256;
            int row = c >> 3, seg = c & 7;
            CP_ASYNC16(smb + (uint32_t)(18432 + row * 72 + seg * 8) * 2,
                       qg + (size_t)row * 64 + seg * 8);
        }
        CP_COMMIT(); CP_WAIT(0);
    }
    __syncthreads();

    uint32_t qa[4][4];
    #pragma unroll
    for (int s = 0; s < 4; s++) {
        uint32_t addr = pw_base + (uint32_t)(l16 * 72 + s * 16 + lh * 8) * 2;
        LDMATRIX_X4(qa[s][0], qa[s][1], qa[s][2], qa[s][3], addr);
    }

    float o[8][4];
    #pragma unroll
    for (int i = 0; i < 8; i++)
        #pragma unroll
        for (int j = 0; j < 4; j++) o[i][j] = 0.0f;
    float m0 = -INFINITY, m1 = -INFINITY, l0 = 0.0f, l1 = 0.0f;

    const int qrow  = qb * 128 + wq * 16 + fr;
    const int qwmin = qb * 128 + wq * 16;
    const int qwmax = qwmin + 15;
    const int cnt   = 2 * qb + 2;

    auto stage_kv = [&](int kt, int buf) {
        const __half* kk = kg + (size_t)(kt * 64) * 64;
        const __half* vv = vg + (size_t)(kt * 64) * 64;
        #pragma unroll
        for (int i = 0; i < 2; i++) {
            int c = tid + i * 256;
            int row = c >> 3, seg = c & 7;
            CP_ASYNC16(smb + (uint32_t)(buf * 4608 + row * 72 + seg * 8) * 2,
                       kk + (size_t)row * 64 + seg * 8);
            CP_ASYNC16(smb + (uint32_t)(9216 + buf * 4608 + row * 72 + seg * 8) * 2,
                       vv + (size_t)row * 64 + seg * 8);
        }
    };

    stage_kv(0, 0);
    CP_COMMIT();

    for (int kt = 0; kt < cnt; kt++) {
        const int buf = kt & 1;
        if (kt + 1 < cnt) {
            stage_kv(kt + 1, buf ^ 1);
            CP_COMMIT();
            CP_WAIT(1);
        } else {
            CP_WAIT(0);
        }
        __syncthreads();

        if (kt * 64 <= qwmax) {
            const uint32_t kb_base = smb + (uint32_t)(buf * 4608) * 2;
            const uint32_t vb_base = smb + (uint32_t)(9216 + buf * 4608) * 2;

            float sc[8][4];
            #pragma unroll
            for (int nt = 0; nt < 8; nt++)
                sc[nt][0] = sc[nt][1] = sc[nt][2] = sc[nt][3] = 0.0f;
            #pragma unroll
            for (int s = 0; s < 4; s++) {
                #pragma unroll
                for (int np = 0; np < 4; np++) {
                    uint32_t r0, r1, r2, r3;
                    uint32_t addr = kb_base +
                        (uint32_t)((np * 16 + l16) * 72 + s * 16 + lh * 8) * 2;
                    LDMATRIX_X4(r0, r1, r2, r3, addr);
                    uint32_t b0[2] = {r0, r2};
                    uint32_t b1[2] = {r1, r3};
                    MMA_F16(sc[2 * np],     qa[s], b0);
                    MMA_F16(sc[2 * np + 1], qa[s], b1);
                }
            }

            if (kt * 64 + 63 > qwmin) {
                #pragma unroll
                for (int nt = 0; nt < 8; nt++) {
                    int colb = kt * 64 + nt * 8 + 2 * fc;
                    if (colb     > qrow)     sc[nt][0] = -1e30f;
                    if (colb + 1 > qrow)     sc[nt][1] = -1e30f;
                    if (colb     > qrow + 8) sc[nt][2] = -1e30f;
                    if (colb + 1 > qrow + 8) sc[nt][3] = -1e30f;
                }
            }

            float t0 = -1e30f, t1 = -1e30f;
            #pragma unroll
            for (int nt = 0; nt < 8; nt++) {
                t0 = fmaxf(t0, fmaxf(sc[nt][0], sc[nt][1]));
                t1 = fmaxf(t1, fmaxf(sc[nt][2], sc[nt][3]));
            }
            t0 = fmaxf(t0, __shfl_xor_sync(0xffffffffu, t0, 1));
            t0 = fmaxf(t0, __shfl_xor_sync(0xffffffffu, t0, 2));
            t1 = fmaxf(t1, __shfl_xor_sync(0xffffffffu, t1, 1));
            t1 = fmaxf(t1, __shfl_xor_sync(0xffffffffu, t1, 2));

            float mn0 = fmaxf(m0, t0), mn1 = fmaxf(m1, t1);
            float c0 = __expf(m0 - mn0), c1 = __expf(m1 - mn1);
            l0 *= c0; l1 *= c1;
            #pragma unroll
            for (int nd = 0; nd < 8; nd++) {
                o[nd][0] *= c0; o[nd][1] *= c0;
                o[nd][2] *= c1; o[nd][3] *= c1;
            }
            m0 = mn0; m1 = mn1;

            #pragma unroll
            for (int nt = 0; nt < 8; nt++) {
                float p0 = __expf(sc[nt][0] - m0);
                float p1 = __expf(sc[nt][1] - m0);
                float p2 = __expf(sc[nt][2] - m1);
                float p3 = __expf(sc[nt][3] - m1);
                __half2 h01 = __floats2half2_rn(p0, p1);
                __half2 h23 = __floats2half2_rn(p2, p3);
                float2 f01 = __half22float2(h01);
                float2 f23 = __half22float2(h23);
                l0 += f01.x + f01.y; l1 += f23.x + f23.y;
                *(__half2*)&Pw[fr * 72 + nt * 8 + 2 * fc]       = h01;
                *(__half2*)&Pw[(fr + 8) * 72 + nt * 8 + 2 * fc] = h23;
            }
            __syncwarp();

            #pragma unroll
            for (int s = 0; s < 4; s++) {
                uint32_t pa[4];
                uint32_t paddr = pw_base + (uint32_t)(l16 * 72 + s * 16 + lh * 8) * 2;
                LDMATRIX_X4(pa[0], pa[1], pa[2], pa[3], paddr);
                #pragma unroll
                for (int ndp = 0; ndp < 4; ndp++) {
                    uint32_t addr = vb_base +
                        (uint32_t)((s * 16 + l16) * 72 + ndp * 16 + lh * 8) * 2;
                    uint32_t r0, r1, r2, r3;
                    LDMATRIX_X4_TRANS(r0, r1, r2, r3, addr);
                    uint32_t b0[2] = {r0, r1};
                    uint32_t b1[2] = {r2, r3};
                    MMA_F16(o[2 * ndp],     pa, b0);
                    MMA_F16(o[2 * ndp + 1], pa, b1);
                }
            }
        }
        __syncthreads();
    }

    l0 += __shfl_xor_sync(0xffffffffu, l0, 1);
    l0 += __shfl_xor_sync(0xffffffffu, l0, 2);
    l1 += __shfl_xor_sync(0xffffffffu, l1, 1);
    l1 += __shfl_xor_sync(0xffffffffu, l1, 2);
    const float inv0 = 1.0f / l0;
    const float inv1 = 1.0f / l1;

    __half* ctx0 = g_ctx + ((size_t)b * Sc + qrow) * Ec + h * Dc;
    __half* ctx1 = g_ctx + ((size_t)b * Sc + qrow + 8) * Ec + h * Dc;
    #pragma unroll
    for (int nd = 0; nd < 8; nd++) {
        int col = nd * 8 + 2 * fc;
        *(__half2*)&ctx0[col] = __floats2half2_rn(o[nd][0] * inv0, o[nd][1] * inv0);
        *(__half2*)&ctx1[col] = __floats2half2_rn(o[nd][2] * inv1, o[nd][3] * inv1);
    }
}

// ---------------------------------------------------------------------------
// Launch
// ---------------------------------------------------------------------------
extern "C" void kernel_launch(void* const* d_in, const int* in_sizes, int n_in,
                              void* d_out, int out_size)
{
    const float* k  = (const float*)d_in[0];
    const float* v  = (const float*)d_in[1];
    const float* q  = (const float*)d_in[2];
    const float* Wk = (const float*)d_in[3];
    const float* Wv = (const float*)d_in[4];
    const float* Wq = (const float*)d_in[5];
    const float* Wo = (const float*)d_in[6];
    float* out = (float*)d_out;

    cudaFuncSetAttribute(gemm_qkv, cudaFuncAttributeMaxDynamicSharedMemorySize, QKV_SMEM);
    cudaFuncSetAttribute(gemm_out, cudaFuncAttributeMaxDynamicSharedMemorySize, OUT_SMEM);
    cudaFuncSetAttribute(attn_tc_kernel, cudaFuncAttributeMaxDynamicSharedMemorySize,
                         ATTN_SMEM_BYTES);

    cvt_weights_kernel<<<4 * NW8 / 256, 256>>>((const float4*)Wk, (const float4*)Wv,
                                               (const float4*)Wq, (const float4*)Wo);

    gemm_qkv<<<dim3(Ec / NT, Mtot / MT, 3), 256, QKV_SMEM>>>(k, v, q);

    attn_tc_kernel<<<dim3(Sc / 128, Hc, Bc), 256, ATTN_SMEM_BYTES>>>();

    gemm_out<<<dim3(Ec / NT, Mtot / MT), 256, OUT_SMEM>>>(out);
}

// round 12
// speedup vs baseline: 1.0716x; 1.0716x over previous
#include <cuda_runtime.h>
#include <cuda_fp16.h>
#include <math.h>
#include <stdint.h>

// Problem constants
#define Bc 4
#define Sc 2048
#define Ec 1024
#define Hc 16
#define Dc 64
#define Mtot (Bc*Sc)   // 8192
#define Kdim 1024

// GEMM tiling: 128x128 CTA tile, 8 warps (64x32), KT=64 per barrier, 3-stage
#define MT 128
#define NT 128
#define KT2 64
#define KTILES2 (Kdim/KT2)   // 16
#define GPH 72                // smem pitch in halves
#define STAGE_BYTES (MT*GPH*2)        // 18432
#define GEMM_B_OFF  (3*STAGE_BYTES)   // 55296
#define GEMM_SMEM   (6*STAGE_BYTES)   // 110592

// Scratch (allocation-free: __device__ globals)
__device__ __half g_kp[Bc*Hc*Sc*Dc];   // [B,H,S,D]
__device__ __half g_vp[Bc*Hc*Sc*Dc];
__device__ __half g_qp[Bc*Hc*Sc*Dc];   // pre-scaled by 1/8
__device__ __half g_ctx[Bc*Sc*Ec];     // [B,S,E]
__device__ __half g_rA[3*Mtot*Kdim];   // fp16 activations (k,v,q)
__device__ __half g_rW[4*Ec*Ec];       // fp16 weights

// ---------------------------------------------------------------------------
// helpers
// ---------------------------------------------------------------------------
__device__ __forceinline__ uint32_t smem_u32(const void* p) {
    uint32_t a;
    asm("{ .reg .u64 t; cvta.to.shared.u64 t, %1; cvt.u32.u64 %0, t; }" : "=r"(a) : "l"(p));
    return a;
}
#define CP_ASYNC16(dst, src) \
    asm volatile("cp.async.cg.shared.global [%0], [%1], 16;" :: "r"(dst), "l"(src))
#define CP_COMMIT() asm volatile("cp.async.commit_group;" ::: "memory")
#define CP_WAIT(n)  asm volatile("cp.async.wait_group %0;" :: "n"(n) : "memory")

#define MMA_F16(d, a, b) \
    asm volatile("mma.sync.aligned.m16n8k16.row.col.f32.f16.f16.f32 " \
        "{%0,%1,%2,%3}, {%4,%5,%6,%7}, {%8,%9}, {%0,%1,%2,%3};" \
        : "+f"((d)[0]), "+f"((d)[1]), "+f"((d)[2]), "+f"((d)[3]) \
        : "r"((a)[0]), "r"((a)[1]), "r"((a)[2]), "r"((a)[3]), \
          "r"((b)[0]), "r"((b)[1]))

#define LDMATRIX_X4(r0, r1, r2, r3, addr) \
    asm volatile("ldmatrix.sync.aligned.m8n8.x4.shared.b16 {%0,%1,%2,%3}, [%4];" \
        : "=r"(r0), "=r"(r1), "=r"(r2), "=r"(r3) : "r"(addr))

#define LDMATRIX_X4_TRANS(r0, r1, r2, r3, addr) \
    asm volatile("ldmatrix.sync.aligned.m8n8.x4.trans.shared.b16 {%0,%1,%2,%3}, [%4];" \
        : "=r"(r0), "=r"(r1), "=r"(r2), "=r"(r3) : "r"(addr))

__device__ __forceinline__ uint32_t h2u(__half2 h) { return *(uint32_t*)&h; }

// ---------------------------------------------------------------------------
// fused convert: 3 activations + 4 weights, fp32 -> fp16, one launch
// ---------------------------------------------------------------------------
#define NA8 (Mtot*Kdim/8)      // 1048576 chunks per activation
#define NW8 (Ec*Ec/8)          // 131072 chunks per weight
#define CVT_CHUNKS (3*NA8 + 4*NW8)
__global__ __launch_bounds__(256) void cvt_all_kernel(const float4* __restrict__ a0,
                                                      const float4* __restrict__ a1,
                                                      const float4* __restrict__ a2,
                                                      const float4* __restrict__ w0,
                                                      const float4* __restrict__ w1,
                                                      const float4* __restrict__ w2,
                                                      const float4* __restrict__ w3) {
    int i = blockIdx.x * blockDim.x + threadIdx.x;
    const float4* src;
    uint4* dst;
    int idx;
    if (i < 3 * NA8) {
        int t = i >> 20;
        idx = i & (NA8 - 1);
        src = (t == 0) ? a0 : (t == 1) ? a1 : a2;
        dst = (uint4*)(g_rA + (size_t)t * Mtot * Kdim);
    } else {
        int j = i - 3 * NA8;
        int w = j >> 17;
        idx = j & (NW8 - 1);
        src = (w == 0) ? w0 : (w == 1) ? w1 : (w == 2) ? w2 : w3;
        dst = (uint4*)(g_rW + (size_t)w * Ec * Ec);
    }
    float4 x = src[2 * idx], y = src[2 * idx + 1];
    uint4 r;
    r.x = h2u(__floats2half2_rn(x.x, x.y));
    r.y = h2u(__floats2half2_rn(x.z, x.w));
    r.z = h2u(__floats2half2_rn(y.x, y.y));
    r.w = h2u(__floats2half2_rn(y.z, y.w));
    dst[idx] = r;
}

// ---------------------------------------------------------------------------
// Unified fp16 GEMM (R9 config): 128x128 CTA tile, 8 warps (64x32), KT=64,
// 3-stage cp.async, ldmatrix frags. LAYOUT 0: scatter half into [B,H,S,D]
// (z picks tensor+scale). LAYOUT 1: fp32 [M,N].
// ---------------------------------------------------------------------------
template <int LAYOUT>
__global__ __launch_bounds__(256, 2) void gemm_all(float* __restrict__ Cout)
{
    extern __shared__ char smc[];
    const uint32_t smbA = smem_u32(smc);
    const uint32_t smbB = smbA + GEMM_B_OFF;

    const int tid  = threadIdx.x;
    const int wid  = tid >> 5;
    const int lane = tid & 31;
    const int warp_m = wid & 1;
    const int warp_n = wid >> 1;
    const int fr = lane >> 2;
    const int fc = lane & 3;
    const int l16 = lane & 15;
    const int lh  = lane >> 4;

    const int z  = blockIdx.z;
    const int n0 = blockIdx.x * NT;
    const int m0 = blockIdx.y * MT;

    const __half* A = (LAYOUT == 1) ? g_ctx : g_rA + (size_t)z * Mtot * Kdim;
    const __half* W = g_rW + (size_t)((LAYOUT == 1) ? 3 : z) * Ec * Ec;

    auto load_tile = [&](int kt, int buf) {
        const int k0 = kt * KT2;
        #pragma unroll
        for (int i = 0; i < 4; i++) {
            int c = tid + i * 256;
            int row = c >> 3, seg = c & 7;
            CP_ASYNC16(smbA + buf * STAGE_BYTES + row * (GPH * 2) + seg * 16,
                       A + (size_t)(m0 + row) * Kdim + k0 + seg * 8);
            CP_ASYNC16(smbB + buf * STAGE_BYTES + row * (GPH * 2) + seg * 16,
                       W + (size_t)(n0 + row) * Kdim + k0 + seg * 8);
        }
    };

    float acc[4][4][4];
    #pragma unroll
    for (int i = 0; i < 4; i++)
        #pragma unroll
        for (int j = 0; j < 4; j++)
            #pragma unroll
            for (int r = 0; r < 4; r++) acc[i][j][r] = 0.0f;

    load_tile(0, 0); CP_COMMIT();
    load_tile(1, 1); CP_COMMIT();

    int buf = 0, nbuf = 2;
    for (int kt = 0; kt < KTILES2; kt++) {
        CP_WAIT(1);
        __syncthreads();
        if (kt + 2 < KTILES2) load_tile(kt + 2, nbuf);
        CP_COMMIT();

        const uint32_t bA = smbA + buf * STAGE_BYTES;
        const uint32_t bB = smbB + buf * STAGE_BYTES;

        #pragma unroll
        for (int s = 0; s < 4; s++) {
            uint32_t af[4][4], bf[4][2];
            #pragma unroll
            for (int mt = 0; mt < 4; mt++) {
                uint32_t addr = bA + (uint32_t)(warp_m * 64 + mt * 16 + l16) * (GPH * 2)
                                   + (uint32_t)(s * 16 + lh * 8) * 2;
                LDMATRIX_X4(af[mt][0], af[mt][1], af[mt][2], af[mt][3], addr);
            }
            #pragma unroll
            for (int np = 0; np < 2; np++) {
                uint32_t r0, r1, r2, r3;
                uint32_t addr = bB + (uint32_t)(warp_n * 32 + np * 16 + l16) * (GPH * 2)
                                   + (uint32_t)(s * 16 + lh * 8) * 2;
                LDMATRIX_X4(r0, r1, r2, r3, addr);
                bf[2 * np][0] = r0; bf[2 * np][1] = r2;
                bf[2 * np + 1][0] = r1; bf[2 * np + 1][1] = r3;
            }
            #pragma unroll
            for (int mt = 0; mt < 4; mt++)
                #pragma unroll
                for (int nt = 0; nt < 4; nt++)
                    MMA_F16(acc[mt][nt], af[mt], bf[nt]);
        }

        buf = (buf == 2) ? 0 : buf + 1;
        nbuf = (nbuf == 2) ? 0 : nbuf + 1;
    }

    if (LAYOUT == 1) {
        #pragma unroll
        for (int mt = 0; mt < 4; mt++)
            #pragma unroll
            for (int nt = 0; nt < 4; nt++) {
                int n = n0 + warp_n * 32 + nt * 8 + fc * 2;
                #pragma unroll
                for (int hi = 0; hi < 2; hi++) {
                    int m = m0 + warp_m * 64 + mt * 16 + fr + hi * 8;
                    *(float2*)&Cout[(size_t)m * Ec + n] =
                        make_float2(acc[mt][nt][hi * 2], acc[mt][nt][hi * 2 + 1]);
                }
            }
    } else {
        __half* outp = (z == 0) ? g_kp : (z == 1) ? g_vp : g_qp;
        const float scale = (z == 2) ? 0.125f : 1.0f;
        #pragma unroll
        for (int mt = 0; mt < 4; mt++)
            #pragma unroll
            for (int nt = 0; nt < 4; nt++) {
                int n = n0 + warp_n * 32 + nt * 8 + fc * 2;
                #pragma unroll
                for (int hi = 0; hi < 2; hi++) {
                    int m = m0 + warp_m * 64 + mt * 16 + fr + hi * 8;
                    int b = m >> 11, s = m & 2047;
                    int h = n >> 6,  d = n & 63;
                    __half2 hv = __floats2half2_rn(acc[mt][nt][hi * 2] * scale,
                                                   acc[mt][nt][hi * 2 + 1] * scale);
                    *(__half2*)&outp[(size_t)(((b * Hc + h) * Sc) + s) * Dc + d] = hv;
                }
            }
    }
}

// ---------------------------------------------------------------------------
// Tensor-core flash attention (causal), fp16 mma.sync (fp32 accum).
// Block: 128 queries x (b,h); 8 warps (m16 each). KV staged in 128-key stages
// (double-buffered), computed as two 64-key sub-tiles (same arithmetic order
// as before -> bitwise-identical results, half the barriers).
// smem halves: Ks[2][128][72] @0 ; Vs[2][128][72] @18432 ; Pq[128][72] @36864
// ---------------------------------------------------------------------------
#define ATTN_SMEM_BYTES (46080 * 2)   // 92160

__global__ __launch_bounds__(256) void attn_tc_kernel()
{
    extern __shared__ __half sh[];
    const int tid  = threadIdx.x;
    const int wq   = tid >> 5;
    const int lane = tid & 31;
    const int fr   = lane >> 2;
    const int fc   = lane & 3;
    const int l16  = lane & 15;
    const int lh   = lane >> 4;
    const int b    = blockIdx.z;
    const int h    = blockIdx.y;
    const int qb   = (int)(gridDim.x - 1 - blockIdx.x);   // heavy tiles first

    const size_t bh = (size_t)(b * Hc + h) * Sc;
    const __half* kg = g_kp + bh * Dc;
    const __half* vg = g_vp + bh * Dc;

    __half* Pw = sh + 36864 + wq * 16 * 72;
    const uint32_t smb = smem_u32(sh);
    const uint32_t pw_base = smb + (uint32_t)(36864 + wq * 16 * 72) * 2;

    // ---- stage Q tile (128 x 64 halves) into P region ----
    {
        const __half* qg = g_qp + (bh + (size_t)qb * 128) * Dc;
        #pragma unroll
        for (int i = 0; i < 4; i++) {
            int c = tid + i * 256;
            int row = c >> 3, seg = c & 7;
            CP_ASYNC16(smb + (uint32_t)(36864 + row * 72 + seg * 8) * 2,
                       qg + (size_t)row * 64 + seg * 8);
        }
        CP_COMMIT(); CP_WAIT(0);
    }
    __syncthreads();

    // Q a-frags for 4 k16-steps via ldmatrix
    uint32_t qa[4][4];
    #pragma unroll
    for (int s = 0; s < 4; s++) {
        uint32_t addr = pw_base + (uint32_t)(l16 * 72 + s * 16 + lh * 8) * 2;
        LDMATRIX_X4(qa[s][0], qa[s][1], qa[s][2], qa[s][3], addr);
    }

    float o[8][4];
    #pragma unroll
    for (int i = 0; i < 8; i++)
        #pragma unroll
        for (int j = 0; j < 4; j++) o[i][j] = 0.0f;
    float m0 = -INFINITY, m1 = -INFINITY, l0 = 0.0f, l1 = 0.0f;

    const int qrow  = qb * 128 + wq * 16 + fr;
    const int qwmin = qb * 128 + wq * 16;
    const int qwmax = qwmin + 15;
    const int scnt  = qb + 1;    // 128-key stages

    // stage loader: 128 rows x 64 halves for K and V = 1024 chunks each
    auto stage_kv = [&](int st, int buf) {
        const __half* kk = kg + (size_t)(st * 128) * 64;
        const __half* vv = vg + (size_t)(st * 128) * 64;
        #pragma unroll
        for (int i = 0; i < 4; i++) {
            int c = tid + i * 256;          // 0..1023
            int row = c >> 3, seg = c & 7;
            CP_ASYNC16(smb + (uint32_t)(buf * 9216 + row * 72 + seg * 8) * 2,
                       kk + (size_t)row * 64 + seg * 8);
            CP_ASYNC16(smb + (uint32_t)(18432 + buf * 9216 + row * 72 + seg * 8) * 2,
                       vv + (size_t)row * 64 + seg * 8);
        }
    };

    stage_kv(0, 0);
    CP_COMMIT();

    for (int st = 0; st < scnt; st++) {
        const int buf = st & 1;
        if (st + 1 < scnt) {
            stage_kv(st + 1, buf ^ 1);
            CP_COMMIT();
            CP_WAIT(1);
        } else {
            CP_WAIT(0);
        }
        __syncthreads();

        #pragma unroll
        for (int sub = 0; sub < 2; sub++) {
            const int kb0 = st * 128 + sub * 64;    // first key of this sub-tile
            if (kb0 > qwmax) continue;

            const uint32_t kb_base = smb + (uint32_t)(buf * 9216 + sub * 4608) * 2;
            const uint32_t vb_base = smb + (uint32_t)(18432 + buf * 9216 + sub * 4608) * 2;

            // S = Q K^T  (16 x 64 per warp): K b-frags via ldmatrix
            float sc[8][4];
            #pragma unroll
            for (int nt = 0; nt < 8; nt++)
                sc[nt][0] = sc[nt][1] = sc[nt][2] = sc[nt][3] = 0.0f;
            #pragma unroll
            for (int s = 0; s < 4; s++) {
                #pragma unroll
                for (int np = 0; np < 4; np++) {
                    uint32_t r0, r1, r2, r3;
                    uint32_t addr = kb_base +
                        (uint32_t)((np * 16 + l16) * 72 + s * 16 + lh * 8) * 2;
                    LDMATRIX_X4(r0, r1, r2, r3, addr);
                    uint32_t b0[2] = {r0, r2};
                    uint32_t b1[2] = {r1, r3};
                    MMA_F16(sc[2 * np],     qa[s], b0);
                    MMA_F16(sc[2 * np + 1], qa[s], b1);
                }
            }

            // causal mask (only on/above the diagonal band)
            if (kb0 + 63 > qwmin) {
                #pragma unroll
                for (int nt = 0; nt < 8; nt++) {
                    int colb = kb0 + nt * 8 + 2 * fc;
                    if (colb     > qrow)     sc[nt][0] = -1e30f;
                    if (colb + 1 > qrow)     sc[nt][1] = -1e30f;
                    if (colb     > qrow + 8) sc[nt][2] = -1e30f;
                    if (colb + 1 > qrow + 8) sc[nt][3] = -1e30f;
                }
            }

            // row maxes (local + quad shuffle)
            float t0 = -1e30f, t1 = -1e30f;
            #pragma unroll
            for (int nt = 0; nt < 8; nt++) {
                t0 = fmaxf(t0, fmaxf(sc[nt][0], sc[nt][1]));
                t1 = fmaxf(t1, fmaxf(sc[nt][2], sc[nt][3]));
            }
            t0 = fmaxf(t0, __shfl_xor_sync(0xffffffffu, t0, 1));
            t0 = fmaxf(t0, __shfl_xor_sync(0xffffffffu, t0, 2));
            t1 = fmaxf(t1, __shfl_xor_sync(0xffffffffu, t1, 1));
            t1 = fmaxf(t1, __shfl_xor_sync(0xffffffffu, t1, 2));

            float mn0 = fmaxf(m0, t0), mn1 = fmaxf(m1, t1);
            float c0 = __expf(m0 - mn0), c1 = __expf(m1 - mn1);
            l0 *= c0; l1 *= c1;
            #pragma unroll
            for (int nd = 0; nd < 8; nd++) {
                o[nd][0] *= c0; o[nd][1] *= c0;
                o[nd][2] *= c1; o[nd][3] *= c1;
            }
            m0 = mn0; m1 = mn1;

            // P = exp(S - m) -> half, stash per-warp
            #pragma unroll
            for (int nt = 0; nt < 8; nt++) {
                float p0 = __expf(sc[nt][0] - m0);
                float p1 = __expf(sc[nt][1] - m0);
                float p2 = __expf(sc[nt][2] - m1);
                float p3 = __expf(sc[nt][3] - m1);
                __half2 h01 = __floats2half2_rn(p0, p1);
                __half2 h23 = __floats2half2_rn(p2, p3);
                float2 f01 = __half22float2(h01);
                float2 f23 = __half22float2(h23);
                l0 += f01.x + f01.y; l1 += f23.x + f23.y;
                *(__half2*)&Pw[fr * 72 + nt * 8 + 2 * fc]       = h01;
                *(__half2*)&Pw[(fr + 8) * 72 + nt * 8 + 2 * fc] = h23;
            }
            __syncwarp();

            // O += P V : P a-frags via ldmatrix, V b-frags via ldmatrix.trans
            #pragma unroll
            for (int s = 0; s < 4; s++) {
                uint32_t pa[4];
                uint32_t paddr = pw_base + (uint32_t)(l16 * 72 + s * 16 + lh * 8) * 2;
                LDMATRIX_X4(pa[0], pa[1], pa[2], pa[3], paddr);
                #pragma unroll
                for (int ndp = 0; ndp < 4; ndp++) {
                    uint32_t addr = vb_base +
                        (uint32_t)((s * 16 + l16) * 72 + ndp * 16 + lh * 8) * 2;
                    uint32_t r0, r1, r2, r3;
                    LDMATRIX_X4_TRANS(r0, r1, r2, r3, addr);
                    uint32_t b0[2] = {r0, r1};
                    uint32_t b1[2] = {r2, r3};
                    MMA_F16(o[2 * ndp],     pa, b0);
                    MMA_F16(o[2 * ndp + 1], pa, b1);
                }
            }
        }
        __syncthreads();
    }

    // epilogue
    l0 += __shfl_xor_sync(0xffffffffu, l0, 1);
    l0 += __shfl_xor_sync(0xffffffffu, l0, 2);
    l1 += __shfl_xor_sync(0xffffffffu, l1, 1);
    l1 += __shfl_xor_sync(0xffffffffu, l1, 2);
    const float inv0 = 1.0f / l0;
    const float inv1 = 1.0f / l1;

    __half* ctx0 = g_ctx + ((size_t)b * Sc + qrow) * Ec + h * Dc;
    __half* ctx1 = g_ctx + ((size_t)b * Sc + qrow + 8) * Ec + h * Dc;
    #pragma unroll
    for (int nd = 0; nd < 8; nd++) {
        int col = nd * 8 + 2 * fc;
        *(__half2*)&ctx0[col] = __floats2half2_rn(o[nd][0] * inv0, o[nd][1] * inv0);
        *(__half2*)&ctx1[col] = __floats2half2_rn(o[nd][2] * inv1, o[nd][3] * inv1);
    }
}

// ---------------------------------------------------------------------------
// Launch
// ---------------------------------------------------------------------------
extern "C" void kernel_launch(void* const* d_in, const int* in_sizes, int n_in,
                              void* d_out, int out_size)
{
    const float* k  = (const float*)d_in[0];
    const float* v  = (const float*)d_in[1];
    const float* q  = (const float*)d_in[2];
    const float* Wk = (const float*)d_in[3];
    const float* Wv = (const float*)d_in[4];
    const float* Wq = (const float*)d_in[5];
    const float* Wo = (const float*)d_in[6];
    float* out = (float*)d_out;

    cudaFuncSetAttribute(gemm_all<0>, cudaFuncAttributeMaxDynamicSharedMemorySize, GEMM_SMEM);
    cudaFuncSetAttribute(gemm_all<1>, cudaFuncAttributeMaxDynamicSharedMemorySize, GEMM_SMEM);
    cudaFuncSetAttribute(attn_tc_kernel, cudaFuncAttributeMaxDynamicSharedMemorySize,
                         ATTN_SMEM_BYTES);

    cvt_all_kernel<<<CVT_CHUNKS / 256, 256>>>((const float4*)k, (const float4*)v,
                                              (const float4*)q,
                                              (const float4*)Wk, (const float4*)Wv,
                                              (const float4*)Wq, (const float4*)Wo);

    gemm_all<0><<<dim3(Ec / NT, Mtot / MT, 3), 256, GEMM_SMEM>>>(nullptr);

    attn_tc_kernel<<<dim3(Sc / 128, Hc, Bc), 256, ATTN_SMEM_BYTES>>>();

    gemm_all<1><<<dim3(Ec / NT, Mtot / MT, 1), 256, GEMM_SMEM>>>(out);
}